// round 15
// baseline (speedup 1.0000x reference)
#include <cuda_runtime.h>
#include <cuda_fp16.h>
#include <cstdint>

// Problem constants
#define B_   4
#define S_   2048
#define H_   1024
#define NH_  16
#define HD_  64
#define MROWS (B_ * S_)        // 8192

// softmax folded scale: 1/8 * log2(e)
#define QSCALE 0.18033688011112042f

// ---------------------------------------------------------------------------
// Scratch. All operands single fp16, fp32 accumulation. Q pre-scaled.
// ---------------------------------------------------------------------------
__device__ __half g_xh[(size_t)MROWS * H_];
__device__ __half g_wh[3][(size_t)H_ * H_];
__device__ __half g_qh[(size_t)B_ * NH_ * S_ * HD_];
__device__ __half g_kh[(size_t)B_ * NH_ * S_ * HD_];
__device__ __half g_vh[(size_t)B_ * NH_ * S_ * HD_];

// ---------------------------------------------------------------------------
// helpers
// ---------------------------------------------------------------------------
__device__ __forceinline__ void mma_f16(float* d, const uint32_t* a, const uint32_t* b) {
    asm volatile(
        "mma.sync.aligned.m16n8k16.row.col.f32.f16.f16.f32 "
        "{%0,%1,%2,%3},{%4,%5,%6,%7},{%8,%9},{%0,%1,%2,%3};"
        : "+f"(d[0]), "+f"(d[1]), "+f"(d[2]), "+f"(d[3])
        : "r"(a[0]), "r"(a[1]), "r"(a[2]), "r"(a[3]), "r"(b[0]), "r"(b[1]));
}

__device__ __forceinline__ void ldsm4(uint32_t* r, uint32_t addr) {
    asm volatile(
        "ldmatrix.sync.aligned.m8n8.x4.shared.b16 {%0,%1,%2,%3}, [%4];"
        : "=r"(r[0]), "=r"(r[1]), "=r"(r[2]), "=r"(r[3]) : "r"(addr));
}

__device__ __forceinline__ void ldsm4t(uint32_t* r, uint32_t addr) {
    asm volatile(
        "ldmatrix.sync.aligned.m8n8.x4.trans.shared.b16 {%0,%1,%2,%3}, [%4];"
        : "=r"(r[0]), "=r"(r[1]), "=r"(r[2]), "=r"(r[3]) : "r"(addr));
}

__device__ __forceinline__ float ex2(float x) {
    float r;
    asm("ex2.approx.f32 %0, %1;" : "=f"(r) : "f"(x));
    return r;
}

__device__ __forceinline__ uint32_t ex2h2(uint32_t x) {
    uint32_t r;
    asm("ex2.approx.f16x2 %0, %1;" : "=r"(r) : "r"(x));
    return r;
}

__device__ __forceinline__ __half2 u2h(uint32_t x) {
    __half2 h;
    *(uint32_t*)&h = x;
    return h;
}

__device__ __forceinline__ uint32_t smem_u32(const void* p) {
    uint32_t a;
    asm("{ .reg .u64 tmp; cvta.to.shared.u64 tmp, %1; cvt.u32.u64 %0, tmp; }"
        : "=r"(a) : "l"(p));
    return a;
}

#define CP16(dst, src) \
    asm volatile("cp.async.cg.shared.global [%0], [%1], 16;" \
                 :: "r"(dst), "l"(src) : "memory")
#define CP_COMMIT() asm volatile("cp.async.commit_group;" ::: "memory")
#define CP_WAIT1()  asm volatile("cp.async.wait_group 1;" ::: "memory")

__device__ __forceinline__ uint32_t pack2h(float a, float b) {
    __half2 v = __floats2half2_rn(a, b);
    return *(uint32_t*)&v;
}

// ---------------------------------------------------------------------------
// Kernel 0: merged fp32 -> fp16 prepass (X + Wq + Wk + Wv in one launch).
// ---------------------------------------------------------------------------
#define NX4 (MROWS * H_ / 4)
#define NW4 (H_ * H_ / 4)

__global__ void prep_kernel(const float* __restrict__ x,
                            const float* __restrict__ w0,
                            const float* __restrict__ w1,
                            const float* __restrict__ w2)
{
    int i = blockIdx.x * blockDim.x + threadIdx.x;
    const float* src;
    uint32_t* dst;
    int idx;
    if (i < NX4) {
        src = x; dst = (uint32_t*)g_xh; idx = i;
    } else {
        int j = i - NX4;
        int z = j / NW4;
        idx = j - z * NW4;
        src = (z == 0) ? w0 : (z == 1) ? w1 : w2;
        dst = (uint32_t*)g_wh[z];
    }
    float4 v = ((const float4*)src)[idx];
    dst[idx * 2]     = pack2h(v.x, v.y);
    dst[idx * 2 + 1] = pack2h(v.z, v.w);
}

// ---------------------------------------------------------------------------
// Kernel 1: QKV projection, single-term fp16 HGEMM (fp32 accum).
// CTA 128x128, BK=64, 8 warps (4m x 2n), warp tile 32x64.
// 3-stage cp.async ring, wait_group 1.
// ---------------------------------------------------------------------------
#define GSTR 72
#define GMAT_B 18432
#define GBUF_B 36864
#define QKV_SMEM (3 * GBUF_B)

__global__ __launch_bounds__(256, 2)
void qkv_kernel(const float* __restrict__ bq,
                const float* __restrict__ bk,
                const float* __restrict__ bv)
{
    extern __shared__ char smem[];
    const uint32_t sb = smem_u32(smem);
    const int tid  = threadIdx.x;
    const int lane = tid & 31;
    const int w    = tid >> 5;
    const int wm = (w >> 1) * 32;
    const int wn = (w & 1) * 64;
    const int g = lane >> 2;
    const int t = lane & 3;
    const int lr16 = lane & 15;
    const int lk8  = (lane >> 4) * 8;

    const int z  = blockIdx.z;
    const int n0 = blockIdx.x * 128;
    const int m0 = blockIdx.y * 128;
    const __half* __restrict__ Wh = g_wh[z];
    const float* __restrict__ bias = (z == 0) ? bq : (z == 1) ? bk : bv;

    auto issue = [&](int ck) {
        const int k0 = ck * 64;
        const uint32_t bb = sb + (uint32_t)(ck % 3) * GBUF_B;
        #pragma unroll
        for (int i = 0; i < 4; ++i) {
            const int idx = i * 256 + tid;
            const int r = idx >> 3, c = idx & 7;
            const uint32_t doff = (uint32_t)(r * GSTR + c * 8) * 2;
            CP16(bb + doff,          (const char*)&g_xh[(size_t)(m0 + r) * H_ + k0 + c * 8]);
            CP16(bb + GMAT_B + doff, (const char*)&Wh[(size_t)(n0 + r) * H_ + k0 + c * 8]);
        }
    };

    float acc[2][8][4] = {};

    issue(0); CP_COMMIT();
    issue(1); CP_COMMIT();

    const int NCH = H_ / 64;  // 16
    for (int ck = 0; ck < NCH; ++ck) {
        CP_WAIT1();
        __syncthreads();
        if (ck + 2 < NCH) issue(ck + 2);
        CP_COMMIT();

        const uint32_t bb = sb + (uint32_t)(ck % 3) * GBUF_B;
        #pragma unroll
        for (int ks = 0; ks < 4; ++ks) {
            const uint32_t kc = ks * 16 + lk8;
            uint32_t ah[2][4];
            #pragma unroll
            for (int mt = 0; mt < 2; ++mt) {
                const uint32_t aoff = (uint32_t)((wm + mt * 16 + lr16) * GSTR + kc) * 2;
                ldsm4(ah[mt], bb + aoff);
            }
            #pragma unroll
            for (int np = 0; np < 4; ++np) {
                const uint32_t boff = (uint32_t)((wn + np * 16 + lr16) * GSTR + kc) * 2;
                uint32_t bh4[4];
                ldsm4(bh4, bb + GMAT_B + boff);
                uint32_t be[2] = {bh4[0], bh4[2]};
                uint32_t bo[2] = {bh4[1], bh4[3]};
                #pragma unroll
                for (int mt = 0; mt < 2; ++mt) {
                    mma_f16(acc[mt][2 * np],     ah[mt], be);
                    mma_f16(acc[mt][2 * np + 1], ah[mt], bo);
                }
            }
        }
    }

    // epilogue: bias (+QSCALE for Q) + vectorized head-major store
    const int bidx  = m0 >> 11;
    const int sbase = (m0 & (S_ - 1));
    __half* dst = (z == 0) ? g_qh : (z == 1) ? g_kh : g_vh;
    const float sc = (z == 0) ? QSCALE : 1.0f;
    #pragma unroll
    for (int mt = 0; mt < 2; ++mt) {
        #pragma unroll
        for (int nt = 0; nt < 8; ++nt) {
            const int nloc = wn + nt * 8 + 2 * t;
            const int d    = nloc & 63;
            const int hh   = (n0 + nloc) >> 6;
            const int bh_i = bidx * NH_ + hh;
            const float2 bi = *(const float2*)&bias[n0 + nloc];
            const int s0 = sbase + wm + mt * 16 + g;
            const float v0 = (acc[mt][nt][0] + bi.x) * sc;
            const float v1 = (acc[mt][nt][1] + bi.y) * sc;
            const float v2 = (acc[mt][nt][2] + bi.x) * sc;
            const float v3 = (acc[mt][nt][3] + bi.y) * sc;
            *(uint32_t*)&dst[((size_t)bh_i * S_ + s0) * HD_ + d]     = pack2h(v0, v1);
            *(uint32_t*)&dst[((size_t)bh_i * S_ + s0 + 8) * HD_ + d] = pack2h(v2, v3);
        }
    }
}

// ---------------------------------------------------------------------------
// Kernel 2: causal flash attention, base-2 softmax (Q pre-scaled).
// 3-stage 128-row KV ring (wait_group 1); Q staged in buf2 then reused.
// Warp-uniform causal pruning on diagonal tiles (pmax per 64-half).
// ---------------------------------------------------------------------------
#define QSTR 72
#define ATT_KVSZ 36864u
#define ATT_V 18432u
#define ATT_AM 110592u
#define ATT_SMEM 112128

__global__ __launch_bounds__(256, 2)
void attn_kernel(const float* __restrict__ amask, float* __restrict__ out)
{
    extern __shared__ char smem[];
    const uint32_t sb = smem_u32(smem);
    const int qt = 15 - (int)blockIdx.x;  // heavy tiles first
    const int bh = blockIdx.y;
    const int b  = bh >> 4;
    const int h  = bh & 15;
    const int q0 = qt * 128;
    const int tid  = threadIdx.x;
    const int lane = tid & 31;
    const int w    = tid >> 5;
    const int g = lane >> 2;
    const int t = lane & 3;
    const int lr16 = lane & 15;
    const int lk8  = (lane >> 4) * 8;

    float* sAm = (float*)(smem + ATT_AM);
    const uint32_t ATT_Q = 2u * ATT_KVSZ;   // stage Q in buf2 region

    // Q tile: 128 x 64 fp16 (pre-scaled) into buf2
    #pragma unroll
    for (int i = 0; i < 2; ++i) {
        const int idx = i * 256 + tid;
        const int r = idx >> 2, c = idx & 3;
        *(uint4*)(smem + ATT_Q + (r * QSTR + c * 16) * 2) =
            *(const uint4*)&g_qh[((size_t)bh * S_ + q0 + r) * HD_ + c * 16];
        *(uint4*)(smem + ATT_Q + (r * QSTR + c * 16 + 8) * 2) =
            *(const uint4*)&g_qh[((size_t)bh * S_ + q0 + r) * HD_ + c * 16 + 8];
    }

    auto issue_kv = [&](int kt) {
        const int j0 = kt * 128;
        const uint32_t kb = sb + (uint32_t)(kt % 3) * ATT_KVSZ;
        #pragma unroll
        for (int i = 0; i < 4; ++i) {
            const int idx = i * 256 + tid;
            const int r = idx >> 3, c = idx & 7;
            const uint32_t doff = (uint32_t)(r * QSTR + c * 8) * 2;
            CP16(kb + doff,
                 (const char*)&g_kh[((size_t)bh * S_ + j0 + r) * HD_ + c * 8]);
            CP16(kb + ATT_V + doff,
                 (const char*)&g_vh[((size_t)bh * S_ + j0 + r) * HD_ + c * 8]);
        }
    };

    auto stage_am = [&](int kt) {
        if (tid < 32) {
            float4 a = *(const float4*)&amask[(size_t)b * S_ + kt * 128 + tid * 4];
            a.x *= QSCALE; a.y *= QSCALE; a.z *= QSCALE; a.w *= QSCALE;
            *(float4*)&sAm[(kt % 3) * 128 + tid * 4] = a;
        }
    };

    const int nkv = qt + 1;

    // hoist Q fragments; Q region (buf2) is first overwritten by issue(2),
    // which happens after the iteration-0 barrier (all warps hoisted by then).
    __syncthreads();
    uint32_t q4[4][4];
    #pragma unroll
    for (int ks = 0; ks < 4; ++ks) {
        const uint32_t kc = ks * 16 + lk8;
        const uint32_t qoff = (uint32_t)((w * 16 + lr16) * QSTR + kc) * 2;
        ldsm4(q4[ks], sb + ATT_Q + qoff);
    }

    issue_kv(0); CP_COMMIT();
    stage_am(0);
    if (nkv > 1) { issue_kv(1); stage_am(1); }
    CP_COMMIT();

    float o[8][4] = {};
    float m0r = -1e30f, m1r = -1e30f;
    float l0r = 0.f, l1r = 0.f;
    const int i0 = q0 + w * 16 + g;
    const int i1 = i0 + 8;
    const int imax = q0 + w * 16 + 15;

    for (int kt = 0; kt < nkv; ++kt) {
        CP_WAIT1();
        __syncthreads();
        if (kt + 2 < nkv) { issue_kv(kt + 2); stage_am(kt + 2); }
        CP_COMMIT();

        const uint32_t kb = sb + (uint32_t)(kt % 3) * ATT_KVSZ;

        #pragma unroll
        for (int half = 0; half < 2; ++half) {
            const int j0 = kt * 128 + half * 64;
            if (j0 > imax) continue;   // fully masked for this warp
            const int rbase = half * 64;
            const float* am = sAm + (kt % 3) * 128 + half * 64;

            // warp-uniform causal prune: highest useful 16-col group
            const bool diag = (j0 + 63 > imax - 15);
            int pmax = 3;
            if (diag) { pmax = (imax - j0) >> 4; if (pmax > 3) pmax = 3; }

            // ---- S = Q @ K^T (skip groups beyond pmax) ----
            float s[8][4] = {};
            #pragma unroll
            for (int p = 0; p < 4; ++p) {
                if (p > pmax) continue;
                #pragma unroll
                for (int ks = 0; ks < 4; ++ks) {
                    const uint32_t kc = ks * 16 + lk8;
                    const uint32_t koff =
                        (uint32_t)((rbase + p * 16 + lr16) * QSTR + kc) * 2;
                    uint32_t kh4[4];
                    ldsm4(kh4, kb + koff);
                    uint32_t be[2] = {kh4[0], kh4[2]};
                    uint32_t bo[2] = {kh4[1], kh4[3]};
                    mma_f16(s[2 * p],     q4[ks], be);
                    mma_f16(s[2 * p + 1], q4[ks], bo);
                }
            }

            // ---- mask + online softmax (base-2) ----
            float rm0 = -1e30f, rm1 = -1e30f;
            if (diag) {
                #pragma unroll
                for (int ntj = 0; ntj < 8; ++ntj) {
                    if (ntj > 2 * pmax + 1) { s[ntj][0] = s[ntj][1] = s[ntj][2] = s[ntj][3] = -1e30f; continue; }
                    const float2 amv = *(const float2*)&am[ntj * 8 + 2 * t];
                    const int j = j0 + ntj * 8 + 2 * t;
                    float v0 = s[ntj][0] + amv.x;
                    float v1 = s[ntj][1] + amv.y;
                    float v2 = s[ntj][2] + amv.x;
                    float v3 = s[ntj][3] + amv.y;
                    if (j     > i0) v0 = -1e30f;
                    if (j + 1 > i0) v1 = -1e30f;
                    if (j     > i1) v2 = -1e30f;
                    if (j + 1 > i1) v3 = -1e30f;
                    s[ntj][0] = v0; s[ntj][1] = v1; s[ntj][2] = v2; s[ntj][3] = v3;
                    rm0 = fmaxf(rm0, fmaxf(v0, v1));
                    rm1 = fmaxf(rm1, fmaxf(v2, v3));
                }
            } else {
                #pragma unroll
                for (int ntj = 0; ntj < 8; ++ntj) {
                    const float2 amv = *(const float2*)&am[ntj * 8 + 2 * t];
                    float v0 = s[ntj][0] + amv.x;
                    float v1 = s[ntj][1] + amv.y;
                    float v2 = s[ntj][2] + amv.x;
                    float v3 = s[ntj][3] + amv.y;
                    s[ntj][0] = v0; s[ntj][1] = v1; s[ntj][2] = v2; s[ntj][3] = v3;
                    rm0 = fmaxf(rm0, fmaxf(v0, v1));
                    rm1 = fmaxf(rm1, fmaxf(v2, v3));
                }
            }
            rm0 = fmaxf(rm0, __shfl_xor_sync(0xffffffffu, rm0, 1));
            rm0 = fmaxf(rm0, __shfl_xor_sync(0xffffffffu, rm0, 2));
            rm1 = fmaxf(rm1, __shfl_xor_sync(0xffffffffu, rm1, 1));
            rm1 = fmaxf(rm1, __shfl_xor_sync(0xffffffffu, rm1, 2));

            const float mn0 = fmaxf(m0r, rm0);
            const float mn1 = fmaxf(m1r, rm1);
            const float c0 = ex2(m0r - mn0);
            const float c1 = ex2(m1r - mn1);
            m0r = mn0; m1r = mn1;

            // ---- fused exp + P pack (zeros for pruned groups) ----
            uint32_t pa[4][4];
            #pragma unroll
            for (int ks = 0; ks < 4; ++ks) {
                if (ks > pmax) { pa[ks][0] = pa[ks][1] = pa[ks][2] = pa[ks][3] = 0u; continue; }
                pa[ks][0] = ex2h2(pack2h(s[2 * ks][0]     - mn0, s[2 * ks][1]     - mn0));
                pa[ks][1] = ex2h2(pack2h(s[2 * ks][2]     - mn1, s[2 * ks][3]     - mn1));
                pa[ks][2] = ex2h2(pack2h(s[2 * ks + 1][0] - mn0, s[2 * ks + 1][1] - mn0));
                pa[ks][3] = ex2h2(pack2h(s[2 * ks + 1][2] - mn1, s[2 * ks + 1][3] - mn1));
            }

            // ---- row sums via HADD2 trees ----
            __half2 a0 = __hadd2(__hadd2(u2h(pa[0][0]), u2h(pa[1][0])),
                                 __hadd2(u2h(pa[2][0]), u2h(pa[3][0])));
            __half2 b0 = __hadd2(__hadd2(u2h(pa[0][2]), u2h(pa[1][2])),
                                 __hadd2(u2h(pa[2][2]), u2h(pa[3][2])));
            float2 f0 = __half22float2(__hadd2(a0, b0));
            float rs0 = f0.x + f0.y;

            __half2 a1 = __hadd2(__hadd2(u2h(pa[0][1]), u2h(pa[1][1])),
                                 __hadd2(u2h(pa[2][1]), u2h(pa[3][1])));
            __half2 b1 = __hadd2(__hadd2(u2h(pa[0][3]), u2h(pa[1][3])),
                                 __hadd2(u2h(pa[2][3]), u2h(pa[3][3])));
            float2 f1 = __half22float2(__hadd2(a1, b1));
            float rs1 = f1.x + f1.y;

            rs0 += __shfl_xor_sync(0xffffffffu, rs0, 1);
            rs0 += __shfl_xor_sync(0xffffffffu, rs0, 2);
            rs1 += __shfl_xor_sync(0xffffffffu, rs1, 1);
            rs1 += __shfl_xor_sync(0xffffffffu, rs1, 2);
            l0r = l0r * c0 + rs0;
            l1r = l1r * c1 + rs1;
            #pragma unroll
            for (int ntd = 0; ntd < 8; ++ntd) {
                o[ntd][0] *= c0; o[ntd][1] *= c0;
                o[ntd][2] *= c1; o[ntd][3] *= c1;
            }

            // ---- O += P @ V (skip pruned kv-row groups) ----
            #pragma unroll
            for (int ks = 0; ks < 4; ++ks) {
                if (ks > pmax) continue;
                #pragma unroll
                for (int p = 0; p < 4; ++p) {
                    const uint32_t voff =
                        (uint32_t)((rbase + ks * 16 + lr16) * QSTR + p * 16 + lk8) * 2;
                    uint32_t v4[4];
                    ldsm4t(v4, kb + ATT_V + voff);
                    uint32_t b0v[2] = {v4[0], v4[1]};
                    uint32_t b1v[2] = {v4[2], v4[3]};
                    mma_f16(o[2 * p],     pa[ks], b0v);
                    mma_f16(o[2 * p + 1], pa[ks], b1v);
                }
            }
        }
    }

    // epilogue
    const float inv0 = 1.0f / l0r;
    const float inv1 = 1.0f / l1r;
    #pragma unroll
    for (int ntd = 0; ntd < 8; ++ntd) {
        const int d = h * HD_ + ntd * 8 + 2 * t;
        float2 r0 = make_float2(o[ntd][0] * inv0, o[ntd][1] * inv0);
        float2 r1 = make_float2(o[ntd][2] * inv1, o[ntd][3] * inv1);
        *(float2*)&out[((size_t)b * S_ + i0) * H_ + d] = r0;
        *(float2*)&out[((size_t)b * S_ + i1) * H_ + d] = r1;
    }
}

// ---------------------------------------------------------------------------
// Launch
// ---------------------------------------------------------------------------
extern "C" void kernel_launch(void* const* d_in, const int* in_sizes, int n_in,
                              void* d_out, int out_size)
{
    const float* hidden = (const float*)d_in[0];
    const float* amask  = (const float*)d_in[1];
    const float* Wq = (const float*)d_in[2];
    const float* bq = (const float*)d_in[3];
    const float* Wk = (const float*)d_in[4];
    const float* bk = (const float*)d_in[5];
    const float* Wv = (const float*)d_in[6];
    const float* bv = (const float*)d_in[7];
    float* out = (float*)d_out;

    // merged prepass (1 launch)
    const int ntot = NX4 + 3 * NW4;
    prep_kernel<<<(ntot + 255) / 256, 256>>>(hidden, Wq, Wk, Wv);

    // QKV projection: grid (8 n-tiles, 64 m-tiles, 3)
    cudaFuncSetAttribute(qkv_kernel,
                         cudaFuncAttributeMaxDynamicSharedMemorySize, QKV_SMEM);
    dim3 ggrid(H_ / 128, MROWS / 128, 3);
    qkv_kernel<<<ggrid, 256, QKV_SMEM>>>(bq, bk, bv);

    // attention: grid (16 q-tiles, 64 bh)
    cudaFuncSetAttribute(attn_kernel,
                         cudaFuncAttributeMaxDynamicSharedMemorySize, ATT_SMEM);
    dim3 agrid(S_ / 128, B_ * NH_);
    attn_kernel<<<agrid, 256, ATT_SMEM>>>(amask, out);
}

// round 16
// speedup vs baseline: 1.1519x; 1.1519x over previous
#include <cuda_runtime.h>
#include <cuda_fp16.h>
#include <cstdint>

// Problem constants
#define B_   4
#define S_   2048
#define H_   1024
#define NH_  16
#define HD_  64
#define MROWS (B_ * S_)        // 8192

// softmax folded scale: 1/8 * log2(e)
#define QSCALE 0.18033688011112042f

// ---------------------------------------------------------------------------
// Scratch. All operands single fp16, fp32 accumulation. Q pre-scaled.
// ---------------------------------------------------------------------------
__device__ __half g_xh[(size_t)MROWS * H_];
__device__ __half g_wh[3][(size_t)H_ * H_];
__device__ __half g_qh[(size_t)B_ * NH_ * S_ * HD_];
__device__ __half g_kh[(size_t)B_ * NH_ * S_ * HD_];
__device__ __half g_vh[(size_t)B_ * NH_ * S_ * HD_];

// ---------------------------------------------------------------------------
// helpers
// ---------------------------------------------------------------------------
__device__ __forceinline__ void mma_f16(float* d, const uint32_t* a, const uint32_t* b) {
    asm volatile(
        "mma.sync.aligned.m16n8k16.row.col.f32.f16.f16.f32 "
        "{%0,%1,%2,%3},{%4,%5,%6,%7},{%8,%9},{%0,%1,%2,%3};"
        : "+f"(d[0]), "+f"(d[1]), "+f"(d[2]), "+f"(d[3])
        : "r"(a[0]), "r"(a[1]), "r"(a[2]), "r"(a[3]), "r"(b[0]), "r"(b[1]));
}

__device__ __forceinline__ void ldsm4(uint32_t* r, uint32_t addr) {
    asm volatile(
        "ldmatrix.sync.aligned.m8n8.x4.shared.b16 {%0,%1,%2,%3}, [%4];"
        : "=r"(r[0]), "=r"(r[1]), "=r"(r[2]), "=r"(r[3]) : "r"(addr));
}

__device__ __forceinline__ void ldsm4t(uint32_t* r, uint32_t addr) {
    asm volatile(
        "ldmatrix.sync.aligned.m8n8.x4.trans.shared.b16 {%0,%1,%2,%3}, [%4];"
        : "=r"(r[0]), "=r"(r[1]), "=r"(r[2]), "=r"(r[3]) : "r"(addr));
}

__device__ __forceinline__ float ex2(float x) {
    float r;
    asm("ex2.approx.f32 %0, %1;" : "=f"(r) : "f"(x));
    return r;
}

__device__ __forceinline__ uint32_t ex2h2(uint32_t x) {
    uint32_t r;
    asm("ex2.approx.f16x2 %0, %1;" : "=r"(r) : "r"(x));
    return r;
}

__device__ __forceinline__ __half2 u2h(uint32_t x) {
    __half2 h;
    *(uint32_t*)&h = x;
    return h;
}

__device__ __forceinline__ uint32_t smem_u32(const void* p) {
    uint32_t a;
    asm("{ .reg .u64 tmp; cvta.to.shared.u64 tmp, %1; cvt.u32.u64 %0, tmp; }"
        : "=r"(a) : "l"(p));
    return a;
}

#define CP16(dst, src) \
    asm volatile("cp.async.cg.shared.global [%0], [%1], 16;" \
                 :: "r"(dst), "l"(src) : "memory")
#define CP_COMMIT() asm volatile("cp.async.commit_group;" ::: "memory")
#define CP_WAIT1()  asm volatile("cp.async.wait_group 1;" ::: "memory")

__device__ __forceinline__ uint32_t pack2h(float a, float b) {
    __half2 v = __floats2half2_rn(a, b);
    return *(uint32_t*)&v;
}

// ---------------------------------------------------------------------------
// Kernel 0: merged fp32 -> fp16 prepass (X + Wq + Wk + Wv in one launch).
// ---------------------------------------------------------------------------
#define NX4 (MROWS * H_ / 4)
#define NW4 (H_ * H_ / 4)

__global__ void prep_kernel(const float* __restrict__ x,
                            const float* __restrict__ w0,
                            const float* __restrict__ w1,
                            const float* __restrict__ w2)
{
    int i = blockIdx.x * blockDim.x + threadIdx.x;
    const float* src;
    uint32_t* dst;
    int idx;
    if (i < NX4) {
        src = x; dst = (uint32_t*)g_xh; idx = i;
    } else {
        int j = i - NX4;
        int z = j / NW4;
        idx = j - z * NW4;
        src = (z == 0) ? w0 : (z == 1) ? w1 : w2;
        dst = (uint32_t*)g_wh[z];
    }
    float4 v = ((const float4*)src)[idx];
    dst[idx * 2]     = pack2h(v.x, v.y);
    dst[idx * 2 + 1] = pack2h(v.z, v.w);
}

// ---------------------------------------------------------------------------
// Kernel 1: QKV projection, single-term fp16 HGEMM (fp32 accum).
// CTA 128x128, BK=64, 8 warps (4m x 2n), warp tile 32x64.
// 3-stage cp.async ring, wait_group 1 (2 loads in flight).
// ---------------------------------------------------------------------------
#define GSTR 72
#define GMAT_B 18432
#define GBUF_B 36864
#define QKV_SMEM (3 * GBUF_B)

__global__ __launch_bounds__(256, 2)
void qkv_kernel(const float* __restrict__ bq,
                const float* __restrict__ bk,
                const float* __restrict__ bv)
{
    extern __shared__ char smem[];
    const uint32_t sb = smem_u32(smem);
    const int tid  = threadIdx.x;
    const int lane = tid & 31;
    const int w    = tid >> 5;
    const int wm = (w >> 1) * 32;
    const int wn = (w & 1) * 64;
    const int g = lane >> 2;
    const int t = lane & 3;
    const int lr16 = lane & 15;
    const int lk8  = (lane >> 4) * 8;

    const int z  = blockIdx.z;
    const int n0 = blockIdx.x * 128;
    const int m0 = blockIdx.y * 128;
    const __half* __restrict__ Wh = g_wh[z];
    const float* __restrict__ bias = (z == 0) ? bq : (z == 1) ? bk : bv;

    auto issue = [&](int ck) {
        const int k0 = ck * 64;
        const uint32_t bb = sb + (uint32_t)(ck % 3) * GBUF_B;
        #pragma unroll
        for (int i = 0; i < 4; ++i) {
            const int idx = i * 256 + tid;
            const int r = idx >> 3, c = idx & 7;
            const uint32_t doff = (uint32_t)(r * GSTR + c * 8) * 2;
            CP16(bb + doff,          (const char*)&g_xh[(size_t)(m0 + r) * H_ + k0 + c * 8]);
            CP16(bb + GMAT_B + doff, (const char*)&Wh[(size_t)(n0 + r) * H_ + k0 + c * 8]);
        }
    };

    float acc[2][8][4] = {};

    issue(0); CP_COMMIT();
    issue(1); CP_COMMIT();

    const int NCH = H_ / 64;  // 16
    for (int ck = 0; ck < NCH; ++ck) {
        CP_WAIT1();
        __syncthreads();
        if (ck + 2 < NCH) issue(ck + 2);
        CP_COMMIT();

        const uint32_t bb = sb + (uint32_t)(ck % 3) * GBUF_B;
        #pragma unroll
        for (int ks = 0; ks < 4; ++ks) {
            const uint32_t kc = ks * 16 + lk8;
            uint32_t ah[2][4];
            #pragma unroll
            for (int mt = 0; mt < 2; ++mt) {
                const uint32_t aoff = (uint32_t)((wm + mt * 16 + lr16) * GSTR + kc) * 2;
                ldsm4(ah[mt], bb + aoff);
            }
            #pragma unroll
            for (int np = 0; np < 4; ++np) {
                const uint32_t boff = (uint32_t)((wn + np * 16 + lr16) * GSTR + kc) * 2;
                uint32_t bh4[4];
                ldsm4(bh4, bb + GMAT_B + boff);
                uint32_t be[2] = {bh4[0], bh4[2]};
                uint32_t bo[2] = {bh4[1], bh4[3]};
                #pragma unroll
                for (int mt = 0; mt < 2; ++mt) {
                    mma_f16(acc[mt][2 * np],     ah[mt], be);
                    mma_f16(acc[mt][2 * np + 1], ah[mt], bo);
                }
            }
        }
    }

    // epilogue: bias (+QSCALE for Q) + vectorized head-major store
    const int bidx  = m0 >> 11;
    const int sbase = (m0 & (S_ - 1));
    __half* dst = (z == 0) ? g_qh : (z == 1) ? g_kh : g_vh;
    const float sc = (z == 0) ? QSCALE : 1.0f;
    #pragma unroll
    for (int mt = 0; mt < 2; ++mt) {
        #pragma unroll
        for (int nt = 0; nt < 8; ++nt) {
            const int nloc = wn + nt * 8 + 2 * t;
            const int d    = nloc & 63;
            const int hh   = (n0 + nloc) >> 6;
            const int bh_i = bidx * NH_ + hh;
            const float2 bi = *(const float2*)&bias[n0 + nloc];
            const int s0 = sbase + wm + mt * 16 + g;
            const float v0 = (acc[mt][nt][0] + bi.x) * sc;
            const float v1 = (acc[mt][nt][1] + bi.y) * sc;
            const float v2 = (acc[mt][nt][2] + bi.x) * sc;
            const float v3 = (acc[mt][nt][3] + bi.y) * sc;
            *(uint32_t*)&dst[((size_t)bh_i * S_ + s0) * HD_ + d]     = pack2h(v0, v1);
            *(uint32_t*)&dst[((size_t)bh_i * S_ + s0 + 8) * HD_ + d] = pack2h(v2, v3);
        }
    }
}

// ---------------------------------------------------------------------------
// Kernel 2: causal flash attention, base-2 softmax (Q pre-scaled).
// 3-stage 128-row KV ring (wait_group 1); Q staged in buf2 then reused.
// Grid (bh, qtile): qt decreases with blockIdx.y so CTAs launch in globally
// descending work order (optimal LPT packing for the greedy scheduler).
// ---------------------------------------------------------------------------
#define QSTR 72
#define ATT_KVSZ 36864u
#define ATT_V 18432u
#define ATT_AM 110592u
#define ATT_SMEM 112128

__global__ __launch_bounds__(256, 2)
void attn_kernel(const float* __restrict__ amask, float* __restrict__ out)
{
    extern __shared__ char smem[];
    const uint32_t sb = smem_u32(smem);
    const int qt = 15 - (int)blockIdx.y;  // globally heavy tiles first
    const int bh = blockIdx.x;
    const int b  = bh >> 4;
    const int h  = bh & 15;
    const int q0 = qt * 128;
    const int tid  = threadIdx.x;
    const int lane = tid & 31;
    const int w    = tid >> 5;
    const int g = lane >> 2;
    const int t = lane & 3;
    const int lr16 = lane & 15;
    const int lk8  = (lane >> 4) * 8;

    float* sAm = (float*)(smem + ATT_AM);
    const uint32_t ATT_Q = 2u * ATT_KVSZ;   // stage Q in buf2 region

    // Q tile: 128 x 64 fp16 (pre-scaled) into buf2
    #pragma unroll
    for (int i = 0; i < 2; ++i) {
        const int idx = i * 256 + tid;
        const int r = idx >> 2, c = idx & 3;
        *(uint4*)(smem + ATT_Q + (r * QSTR + c * 16) * 2) =
            *(const uint4*)&g_qh[((size_t)bh * S_ + q0 + r) * HD_ + c * 16];
        *(uint4*)(smem + ATT_Q + (r * QSTR + c * 16 + 8) * 2) =
            *(const uint4*)&g_qh[((size_t)bh * S_ + q0 + r) * HD_ + c * 16 + 8];
    }

    auto issue_kv = [&](int kt) {
        const int j0 = kt * 128;
        const uint32_t kb = sb + (uint32_t)(kt % 3) * ATT_KVSZ;
        #pragma unroll
        for (int i = 0; i < 4; ++i) {
            const int idx = i * 256 + tid;
            const int r = idx >> 3, c = idx & 7;
            const uint32_t doff = (uint32_t)(r * QSTR + c * 8) * 2;
            CP16(kb + doff,
                 (const char*)&g_kh[((size_t)bh * S_ + j0 + r) * HD_ + c * 8]);
            CP16(kb + ATT_V + doff,
                 (const char*)&g_vh[((size_t)bh * S_ + j0 + r) * HD_ + c * 8]);
        }
    };

    auto stage_am = [&](int kt) {
        if (tid < 32) {
            float4 a = *(const float4*)&amask[(size_t)b * S_ + kt * 128 + tid * 4];
            a.x *= QSCALE; a.y *= QSCALE; a.z *= QSCALE; a.w *= QSCALE;
            *(float4*)&sAm[(kt % 3) * 128 + tid * 4] = a;
        }
    };

    const int nkv = qt + 1;   // number of 128-row kv buffers

    // hoist Q fragments; Q region (buf2) is first overwritten by issue(2),
    // which happens after the iteration-0 barrier (all warps hoisted by then).
    __syncthreads();
    uint32_t q4[4][4];
    #pragma unroll
    for (int ks = 0; ks < 4; ++ks) {
        const uint32_t kc = ks * 16 + lk8;
        const uint32_t qoff = (uint32_t)((w * 16 + lr16) * QSTR + kc) * 2;
        ldsm4(q4[ks], sb + ATT_Q + qoff);
    }

    issue_kv(0); CP_COMMIT();
    stage_am(0);
    if (nkv > 1) { issue_kv(1); stage_am(1); }
    CP_COMMIT();

    float o[8][4] = {};
    float m0r = -1e30f, m1r = -1e30f;
    float l0r = 0.f, l1r = 0.f;
    const int i0 = q0 + w * 16 + g;
    const int i1 = i0 + 8;
    const int imax = q0 + w * 16 + 15;

    for (int kt = 0; kt < nkv; ++kt) {
        CP_WAIT1();
        __syncthreads();
        if (kt + 2 < nkv) { issue_kv(kt + 2); stage_am(kt + 2); }
        CP_COMMIT();

        const uint32_t kb = sb + (uint32_t)(kt % 3) * ATT_KVSZ;

        #pragma unroll
        for (int half = 0; half < 2; ++half) {
            const int j0 = kt * 128 + half * 64;
            if (j0 > imax) continue;   // fully masked for this warp
            const int rbase = half * 64;
            const float* am = sAm + (kt % 3) * 128 + half * 64;

            // ---- S = Q @ K^T ----
            float s[8][4] = {};
            #pragma unroll
            for (int ks = 0; ks < 4; ++ks) {
                const uint32_t kc = ks * 16 + lk8;
                #pragma unroll
                for (int p = 0; p < 4; ++p) {
                    const uint32_t koff =
                        (uint32_t)((rbase + p * 16 + lr16) * QSTR + kc) * 2;
                    uint32_t kh4[4];
                    ldsm4(kh4, kb + koff);
                    uint32_t be[2] = {kh4[0], kh4[2]};
                    uint32_t bo[2] = {kh4[1], kh4[3]};
                    mma_f16(s[2 * p],     q4[ks], be);
                    mma_f16(s[2 * p + 1], q4[ks], bo);
                }
            }

            // ---- mask + online softmax (base-2) ----
            float rm0 = -1e30f, rm1 = -1e30f;
            if (j0 + 63 > imax - 15) {
                #pragma unroll
                for (int ntj = 0; ntj < 8; ++ntj) {
                    const float2 amv = *(const float2*)&am[ntj * 8 + 2 * t];
                    const int j = j0 + ntj * 8 + 2 * t;
                    float v0 = s[ntj][0] + amv.x;
                    float v1 = s[ntj][1] + amv.y;
                    float v2 = s[ntj][2] + amv.x;
                    float v3 = s[ntj][3] + amv.y;
                    if (j     > i0) v0 = -1e30f;
                    if (j + 1 > i0) v1 = -1e30f;
                    if (j     > i1) v2 = -1e30f;
                    if (j + 1 > i1) v3 = -1e30f;
                    s[ntj][0] = v0; s[ntj][1] = v1; s[ntj][2] = v2; s[ntj][3] = v3;
                    rm0 = fmaxf(rm0, fmaxf(v0, v1));
                    rm1 = fmaxf(rm1, fmaxf(v2, v3));
                }
            } else {
                #pragma unroll
                for (int ntj = 0; ntj < 8; ++ntj) {
                    const float2 amv = *(const float2*)&am[ntj * 8 + 2 * t];
                    float v0 = s[ntj][0] + amv.x;
                    float v1 = s[ntj][1] + amv.y;
                    float v2 = s[ntj][2] + amv.x;
                    float v3 = s[ntj][3] + amv.y;
                    s[ntj][0] = v0; s[ntj][1] = v1; s[ntj][2] = v2; s[ntj][3] = v3;
                    rm0 = fmaxf(rm0, fmaxf(v0, v1));
                    rm1 = fmaxf(rm1, fmaxf(v2, v3));
                }
            }
            rm0 = fmaxf(rm0, __shfl_xor_sync(0xffffffffu, rm0, 1));
            rm0 = fmaxf(rm0, __shfl_xor_sync(0xffffffffu, rm0, 2));
            rm1 = fmaxf(rm1, __shfl_xor_sync(0xffffffffu, rm1, 1));
            rm1 = fmaxf(rm1, __shfl_xor_sync(0xffffffffu, rm1, 2));

            const float mn0 = fmaxf(m0r, rm0);
            const float mn1 = fmaxf(m1r, rm1);
            const float c0 = ex2(m0r - mn0);
            const float c1 = ex2(m1r - mn1);
            m0r = mn0; m1r = mn1;

            // ---- fused exp + P pack ----
            uint32_t pa[4][4];
            #pragma unroll
            for (int ks = 0; ks < 4; ++ks) {
                pa[ks][0] = ex2h2(pack2h(s[2 * ks][0]     - mn0, s[2 * ks][1]     - mn0));
                pa[ks][1] = ex2h2(pack2h(s[2 * ks][2]     - mn1, s[2 * ks][3]     - mn1));
                pa[ks][2] = ex2h2(pack2h(s[2 * ks + 1][0] - mn0, s[2 * ks + 1][1] - mn0));
                pa[ks][3] = ex2h2(pack2h(s[2 * ks + 1][2] - mn1, s[2 * ks + 1][3] - mn1));
            }

            // ---- row sums via HADD2 trees ----
            __half2 a0 = __hadd2(__hadd2(u2h(pa[0][0]), u2h(pa[1][0])),
                                 __hadd2(u2h(pa[2][0]), u2h(pa[3][0])));
            __half2 b0 = __hadd2(__hadd2(u2h(pa[0][2]), u2h(pa[1][2])),
                                 __hadd2(u2h(pa[2][2]), u2h(pa[3][2])));
            float2 f0 = __half22float2(__hadd2(a0, b0));
            float rs0 = f0.x + f0.y;

            __half2 a1 = __hadd2(__hadd2(u2h(pa[0][1]), u2h(pa[1][1])),
                                 __hadd2(u2h(pa[2][1]), u2h(pa[3][1])));
            __half2 b1 = __hadd2(__hadd2(u2h(pa[0][3]), u2h(pa[1][3])),
                                 __hadd2(u2h(pa[2][3]), u2h(pa[3][3])));
            float2 f1 = __half22float2(__hadd2(a1, b1));
            float rs1 = f1.x + f1.y;

            rs0 += __shfl_xor_sync(0xffffffffu, rs0, 1);
            rs0 += __shfl_xor_sync(0xffffffffu, rs0, 2);
            rs1 += __shfl_xor_sync(0xffffffffu, rs1, 1);
            rs1 += __shfl_xor_sync(0xffffffffu, rs1, 2);
            l0r = l0r * c0 + rs0;
            l1r = l1r * c1 + rs1;
            #pragma unroll
            for (int ntd = 0; ntd < 8; ++ntd) {
                o[ntd][0] *= c0; o[ntd][1] *= c0;
                o[ntd][2] *= c1; o[ntd][3] *= c1;
            }

            // ---- O += P @ V (B-fragments via ldmatrix.trans) ----
            #pragma unroll
            for (int ks = 0; ks < 4; ++ks) {
                #pragma unroll
                for (int p = 0; p < 4; ++p) {
                    const uint32_t voff =
                        (uint32_t)((rbase + ks * 16 + lr16) * QSTR + p * 16 + lk8) * 2;
                    uint32_t v4[4];
                    ldsm4t(v4, kb + ATT_V + voff);
                    uint32_t b0v[2] = {v4[0], v4[1]};
                    uint32_t b1v[2] = {v4[2], v4[3]};
                    mma_f16(o[2 * p],     pa[ks], b0v);
                    mma_f16(o[2 * p + 1], pa[ks], b1v);
                }
            }
        }
    }

    // epilogue
    const float inv0 = 1.0f / l0r;
    const float inv1 = 1.0f / l1r;
    #pragma unroll
    for (int ntd = 0; ntd < 8; ++ntd) {
        const int d = h * HD_ + ntd * 8 + 2 * t;
        float2 r0 = make_float2(o[ntd][0] * inv0, o[ntd][1] * inv0);
        float2 r1 = make_float2(o[ntd][2] * inv1, o[ntd][3] * inv1);
        *(float2*)&out[((size_t)b * S_ + i0) * H_ + d] = r0;
        *(float2*)&out[((size_t)b * S_ + i1) * H_ + d] = r1;
    }
}

// ---------------------------------------------------------------------------
// Launch
// ---------------------------------------------------------------------------
extern "C" void kernel_launch(void* const* d_in, const int* in_sizes, int n_in,
                              void* d_out, int out_size)
{
    const float* hidden = (const float*)d_in[0];
    const float* amask  = (const float*)d_in[1];
    const float* Wq = (const float*)d_in[2];
    const float* bq = (const float*)d_in[3];
    const float* Wk = (const float*)d_in[4];
    const float* bk = (const float*)d_in[5];
    const float* Wv = (const float*)d_in[6];
    const float* bv = (const float*)d_in[7];
    float* out = (float*)d_out;

    // merged prepass (1 launch)
    const int ntot = NX4 + 3 * NW4;
    prep_kernel<<<(ntot + 255) / 256, 256>>>(hidden, Wq, Wk, Wv);

    // QKV projection: grid (8 n-tiles, 64 m-tiles, 3)
    cudaFuncSetAttribute(qkv_kernel,
                         cudaFuncAttributeMaxDynamicSharedMemorySize, QKV_SMEM);
    dim3 ggrid(H_ / 128, MROWS / 128, 3);
    qkv_kernel<<<ggrid, 256, QKV_SMEM>>>(bq, bk, bv);

    // attention: grid (64 bh, 16 q-tiles) — globally descending work order
    cudaFuncSetAttribute(attn_kernel,
                         cudaFuncAttributeMaxDynamicSharedMemorySize, ATT_SMEM);
    dim3 agrid(B_ * NH_, S_ / 128);
    attn_kernel<<<agrid, 256, ATT_SMEM>>>(amask, out);
}